// round 15
// baseline (speedup 1.0000x reference)
#include <cuda_runtime.h>
#include <math.h>

// ---------------------------------------------------------------------------
// MetaLearner: coordinate-wise LSTM learned optimizer, 16 sequential steps.
// Round-14 base + unclamped MUFU tanh + packed f/i partial accumulation.
// ---------------------------------------------------------------------------

#define D 512
#define C 256
#define U 40
#define T 16
#define B 64
#define P 131072
#define NZ 160              // 4*U
#define KE 43               // 3 + U   (l0,l1 folded into bias)
#define PREP 10.0f

#define NEGEXPP 4.5399929762484854e-05f   // exp(-10)
#define EXPP    22026.465794806718f       // exp(+10)

#define NBLK_C 444          // 3 blocks per SM

// ---------------- persistent state (no allocations allowed) ----------------
// hc interleaved: per (u, coord-pair) a float4 (c0, c1, h0, h1).
__device__ float4 g_hc[(size_t)U * (P / 2)];
__device__ float g_p[P];
__device__ float2 g_fi[P];               // (f, i)
__device__ __align__(16) float g_e[B * C];
__device__ float g_losspart[256];

// ---------------------------------------------------------------------------
// Unclamped MUFU tanh: ex2.approx(+inf)->inf, rcp.approx(inf)->0 => +1;
// ex2.approx(-inf)->0 => -1. Finite args only (GEMM outputs).
// ---------------------------------------------------------------------------
__device__ __forceinline__ float tanh_mufu(float x)
{
    float y = x * 2.8853900817779268f;            // 2*log2(e)*x
    float ex;
    asm("ex2.approx.f32 %0, %1;" : "=f"(ex) : "f"(y));  // exp(2x)
    float d = ex + 1.0f;
    float r;
    asm("rcp.approx.f32 %0, %1;" : "=f"(r) : "f"(d));
    return fmaf(-2.0f, r, 1.0f);
}

__device__ __forceinline__ float hsig(float x)
{
    return __saturatef(fmaf(0.2f, x, 0.5f));
}

#define FMA2(acc, a, b) \
    asm("fma.rn.f32x2 %0, %1, %2, %0;" : "+l"(acc) : "l"(a), "l"(b))

__device__ __forceinline__ float2 u2f(unsigned long long v)
{
    float2 r;
    asm("mov.b64 {%0, %1}, %2;" : "=f"(r.x), "=f"(r.y) : "l"(v));
    return r;
}
__device__ __forceinline__ unsigned long long pack2(float a, float b)
{
    unsigned long long v;
    asm("mov.b64 %0, {%1, %2};" : "=l"(v) : "f"(a), "f"(b));
    return v;
}

// ---------------------------------------------------------------------------
// Kernel A: preds/e/loss-partials.  grid 256 = b(64) x col-quarter(4).
// ---------------------------------------------------------------------------
__global__ void __launch_bounds__(256) stepA(
    const float* __restrict__ feats_t,
    const float* __restrict__ labels_t,
    const float* __restrict__ params, int t0)
{
    __shared__ float fr[D];
    __shared__ float4 sred[256];
    int tid = threadIdx.x;
    int b = blockIdx.x >> 2;
    int cq = blockIdx.x & 3;

    fr[tid] = feats_t[b * D + tid];
    fr[tid + 256] = feats_t[b * D + tid + 256];
    __syncthreads();

    const float* pm = t0 ? params : g_p;
    const float4* pm4 = (const float4*)pm;
    int cl = tid & 15, ks = tid >> 4;
    int c4 = cq * 16 + cl;
    float4 acc = make_float4(0.f, 0.f, 0.f, 0.f);
    int dbeg = ks * 32;
#pragma unroll 8
    for (int d = dbeg; d < dbeg + 32; d++) {
        float fv = fr[d];
        float4 w = pm4[d * 64 + c4];
        acc.x = fmaf(fv, w.x, acc.x);
        acc.y = fmaf(fv, w.y, acc.y);
        acc.z = fmaf(fv, w.z, acc.z);
        acc.w = fmaf(fv, w.w, acc.w);
    }
    sred[tid] = acc;
    __syncthreads();

    if (tid < 32) {
        float v = 0.f;
        if (tid < 16) {
            float4 s = sred[tid];
#pragma unroll
            for (int k = 1; k < 16; k++) {
                float4 a = sred[k * 16 + tid];
                s.x += a.x; s.y += a.y; s.z += a.z; s.w += a.w;
            }
            int cc = cq * 16 + tid;
            float4 y = ((const float4*)labels_t)[b * 64 + cc];
            float4 df = make_float4(s.x - y.x, s.y - y.y, s.z - y.z, s.w - y.w);
            const float kc = 2.0f / 16384.0f;
            ((float4*)g_e)[b * 64 + cc] =
                make_float4(df.x * kc, df.y * kc, df.z * kc, df.w * kc);
            v = df.x * df.x + df.y * df.y + df.z * df.z + df.w * df.w;
        }
#pragma unroll
        for (int off = 8; off > 0; off >>= 1)
            v += __shfl_xor_sync(0xffffffffu, v, off);
        if (tid == 0) g_losspart[blockIdx.x] = v;
    }
}

// ---------------------------------------------------------------------------
// Kernel C: grads + LSTM + param update. grid = 444 blocks (3/SM) x 256 thr.
// group tiles {256,512,768,512} -> blocks {56,111,166,111}; 4-5 tiles/block.
// Thread (tn,tm): u-set {tn+8j}, coord pair (2tm,2tm+1). 2 barriers/tile.
// ---------------------------------------------------------------------------
#define WP_ULL    (KE * 8 * 10)              // 3440 ull weight pairs
#define BP_OFF    WP_ULL                     // 80 ull bias pairs
#define WF2_OFF   (WP_ULL + 80)              // 40 ull splatted Wf
#define WI2_OFF   (WF2_OFF + 40)             // 40 ull splatted Wi
#define ULL_TOT   (WI2_OFF + 40)             // 3600
#define F_WF      0
#define F_WI      41
#define F_SCAL    82
#define F_FCOL    88                          // [3][64] = 192
#define F_GBUF    (F_FCOL + 192)              // 320 floats (nc<=320)
#define F_XS      (F_GBUF + 320)              // 600 (even -> 8B aligned)
#define XS_STR    66
#define F_PR      (F_XS + KE * XS_STR)        // 600+2838=3438 (even)
#define F_TOT     (F_PR + 1024)
#define SMEM_C_BYTES (ULL_TOT * 8 + F_TOT * 4)   // 28800+17848=46648

__global__ void __launch_bounds__(256, 3) stepC(
    const float* __restrict__ feats_t, // [64,512]
    const float* __restrict__ kern,    // [4,5,160]
    const float* __restrict__ rkern,   // [4,40,160]
    const float* __restrict__ bias,    // [4,160]
    const float* __restrict__ Wf,      // [4,41]
    const float* __restrict__ bf,      // [4]
    const float* __restrict__ Wi,      // [4,41]
    const float* __restrict__ bi,      // [4]
    const float* __restrict__ params,  // [P]
    float* __restrict__ outp,
    int t0, int last)
{
    extern __shared__ __align__(16) unsigned long long smU[];
    unsigned long long* Wp  = smU;            // [43][8][10]
    unsigned long long* bp  = smU + BP_OFF;   // [8][10]
    unsigned long long* Wf2 = smU + WF2_OFF;  // [40] splatted
    unsigned long long* Wi2 = smU + WI2_OFF;  // [40] splatted
    float* smF  = (float*)(smU + ULL_TOT);
    float* Wf_s = smF + F_WF;
    float* Wi_s = smF + F_WI;
    float* scal = smF + F_SCAL;
    float* fcol = smF + F_FCOL;
    float* gbuf = smF + F_GBUF;
    float* xs   = smF + F_XS;
    float2* prF = (float2*)(smF + F_PR);          // [8][32]
    float2* prI = (float2*)(smF + F_PR + 512);    // [8][32]

    int tid = threadIdx.x;
    int blk = blockIdx.x;

    // ---- block -> (group, tile range) ----
    int grp, bi_, nb, nt, t0g;
    if (blk < 56)       { grp = 0; bi_ = blk;       nb = 56;  nt = 256; t0g = 0;    }
    else if (blk < 167) { grp = 1; bi_ = blk - 56;  nb = 111; nt = 512; t0g = 256;  }
    else if (blk < 333) { grp = 2; bi_ = blk - 167; nb = 166; nt = 768; t0g = 768;  }
    else                { grp = 3; bi_ = blk - 333; nb = 111; nt = 512; t0g = 1536; }
    int q = nt / nb, r = nt % nb;
    int tile_start = t0g + bi_ * q + min(bi_, r);
    int ntiles = q + (bi_ < r ? 1 : 0);          // 4 or 5
    int start64 = tile_start * 64;
    int nc = ntiles * 64;                        // <= 320

    // ---- phase 0a: weights (gate-paired, strided u), Wf/Wi, fcol ----
    if (tid < 41) { Wf_s[tid] = Wf[grp * 41 + tid]; Wi_s[tid] = Wi[grp * 41 + tid]; }
    if (tid == 0) { scal[2] = bf[grp]; scal[3] = bi[grp]; }
    int d_lo = start64 >> 8;
    int d_hi = (start64 + nc - 1) >> 8;
    int nd = d_hi - d_lo + 1;                     // <= 3
    for (int idx = tid; idx < nd * 64; idx += 256) {
        int bb = idx & 63, k = idx >> 6;
        fcol[k * 64 + bb] = feats_t[bb * D + d_lo + k];
    }
    // Wp[k][tn][j]: j=2*uu+p; u = tn + 8*uu; p=0 -> (w_i,w_f); p=1 -> (w_c,w_o)
    for (int idx = tid; idx < KE * 80; idx += 256) {
        int k = idx / 80, j8 = idx - k * 80;
        int tn_ = j8 / 10, j = j8 - tn_ * 10;
        int uu = j >> 1, p = j & 1;
        int u = tn_ + 8 * uu;
        int n0 = (p ? 2 : 0) * 40 + u;
        int n1 = (p ? 3 : 1) * 40 + u;
        const float* src = (k < 3) ? (kern + grp * 800 + k * NZ)
                                   : (rkern + grp * 6400 + (k - 3) * NZ);
        Wp[idx] = pack2(src[n0], src[n1]);
    }
    __syncthreads();

    // ---- phase 0b: loss reduce (warp 0) + grads into gbuf (paired) ----
    if (tid < 32) {
        float v = 0.f;
#pragma unroll
        for (int k = 0; k < 8; k++) v += g_losspart[k * 32 + tid];
#pragma unroll
        for (int off = 16; off > 0; off >>= 1)
            v += __shfl_xor_sync(0xffffffffu, v, off);
        if (tid == 0) {
            float L = v * (1.0f / 16384.0f);
            float a = fabsf(L);
            if (a > NEGEXPP) {
                scal[0] = __logf(a) * (1.0f / PREP);
                scal[1] = (L > 0.f) ? 1.f : ((L < 0.f) ? -1.f : 0.f);
            } else {
                scal[0] = -1.f;
                scal[1] = EXPP * L;
            }
        }
    }
    // one thread per coord PAIR: coords 2*tid, 2*tid+1 (same d always).
    if (tid < nc / 2) {
        int coord0 = start64 + 2 * tid;
        int cc = coord0 & 255;                   // even
        int dk = (coord0 >> 8) - d_lo;
        const float* frow = fcol + dk * 64;
        float acc0 = 0.f, acc1 = 0.f;
#pragma unroll 8
        for (int bb = 0; bb < B; bb++) {
            float2 ev = *(const float2*)(g_e + bb * C + cc);
            float fv = frow[bb];
            acc0 = fmaf(fv, ev.x, acc0);
            acc1 = fmaf(fv, ev.y, acc1);
        }
        gbuf[2 * tid] = acc0;
        gbuf[2 * tid + 1] = acc1;
    }
    __syncthreads();

    // ---- phase 0c: effective bias + splatted Wf/Wi tables ----
    float l0 = scal[0], l1 = scal[1], bfv = scal[2], biv = scal[3];
    if (tid < 80) {
        int tn_ = tid / 10, j = tid - tn_ * 10;
        int uu = j >> 1, p = j & 1;
        int u = tn_ + 8 * uu;
        int n0 = (p ? 2 : 0) * 40 + u;
        int n1 = (p ? 3 : 1) * 40 + u;
        const float* kb = kern + grp * 800;
        float b0 = bias[grp * NZ + n0] + l0 * kb[3 * NZ + n0] + l1 * kb[4 * NZ + n0];
        float b1 = bias[grp * NZ + n1] + l0 * kb[3 * NZ + n1] + l1 * kb[4 * NZ + n1];
        bp[tid] = pack2(b0, b1);
    } else if (tid >= 128 && tid < 168) {
        float w = Wf_s[tid - 128];
        Wf2[tid - 128] = pack2(w, w);
    } else if (tid >= 168 && tid < 208) {
        float w = Wi_s[tid - 168];
        Wi2[tid - 168] = pack2(w, w);
    }

    int tm = tid & 31;            // coord pair (2tm, 2tm+1)
    int tn = tid >> 5;            // u-set {tn + 8j}
    const unsigned long long* wthr = Wp + tn * 10;
    const unsigned long long* bthr = bp + tn * 10;

    for (int it = 0; it < ntiles; it++) {
        int base = start64 + it * 64;
        int rel = it * 64;
        int pbase = base >> 1;                 // hc pair base

        // ---- fill xs + c->regs + epilogue regs (overlaps prev epilogue) ----
        float pold_c = 0.f, gv_c = 0.f, fp_c = 0.f, ip_c = 0.f;
        if (tid < 64) {
            int coord = base + tid;
            pold_c = t0 ? params[coord] : g_p[coord];
            gv_c = gbuf[rel + tid];
            if (!t0) {
                float2 fi = g_fi[coord];
                fp_c = fi.x; ip_c = fi.y;
            }
            float a = fabsf(gv_c);
            float g0, g1;
            if (a > NEGEXPP) {
                g0 = __logf(a) * (1.0f / PREP);
                g1 = (gv_c > 0.f) ? 1.f : ((gv_c < 0.f) ? -1.f : 0.f);
            } else {
                g0 = -1.f;
                g1 = EXPP * gv_c;
            }
            xs[0 * XS_STR + tid] = pold_c;
            xs[1 * XS_STR + tid] = g0;
            xs[2 * XS_STR + tid] = g1;
        }
        float2 cpre[5];
#pragma unroll
        for (int j = 0; j < 5; j++) {
            int u = tn + 8 * j;
            float4 v = t0 ? make_float4(0.f, 0.f, 0.f, 0.f)
                          : g_hc[(size_t)u * (P / 2) + pbase + tm];
            *(float2*)(xs + (3 + u) * XS_STR + 2 * tm) = make_float2(v.z, v.w);
            cpre[j] = make_float2(v.x, v.y);
        }
        __syncthreads();                       // BAR 1: xs ready

        // ---- GEMM: gate-paired FFMA2.  acc[m*10+2uu+p] ----
        unsigned long long acc[20];
#pragma unroll
        for (int j = 0; j < 10; j++) {
            unsigned long long bv = bthr[j];
            acc[j] = bv; acc[10 + j] = bv;
        }
#pragma unroll 2
        for (int k = 0; k < KE; k++) {
            float2 xv = *(const float2*)(xs + k * XS_STR + 2 * tm);
            unsigned long long s0 = pack2(xv.x, xv.x);
            unsigned long long s1 = pack2(xv.y, xv.y);
            const unsigned long long* wp = wthr + k * 80;
            ulonglong2 w01 = *(const ulonglong2*)(wp);
            ulonglong2 w23 = *(const ulonglong2*)(wp + 2);
            ulonglong2 w45 = *(const ulonglong2*)(wp + 4);
            ulonglong2 w67 = *(const ulonglong2*)(wp + 6);
            ulonglong2 w89 = *(const ulonglong2*)(wp + 8);
            FMA2(acc[0], s0, w01.x);  FMA2(acc[10], s1, w01.x);
            FMA2(acc[1], s0, w01.y);  FMA2(acc[11], s1, w01.y);
            FMA2(acc[2], s0, w23.x);  FMA2(acc[12], s1, w23.x);
            FMA2(acc[3], s0, w23.y);  FMA2(acc[13], s1, w23.y);
            FMA2(acc[4], s0, w45.x);  FMA2(acc[14], s1, w45.x);
            FMA2(acc[5], s0, w45.y);  FMA2(acc[15], s1, w45.y);
            FMA2(acc[6], s0, w67.x);  FMA2(acc[16], s1, w67.x);
            FMA2(acc[7], s0, w67.y);  FMA2(acc[17], s1, w67.y);
            FMA2(acc[8], s0, w89.x);  FMA2(acc[18], s1, w89.x);
            FMA2(acc[9], s0, w89.y);  FMA2(acc[19], s1, w89.y);
        }

        // ---- gates + cell update (c from regs) + packed f/i partials ----
        unsigned long long accF = 0ull, accI = 0ull;   // (pf0,pf1),(pi0,pi1)
#pragma unroll
        for (int uu = 0; uu < 5; uu++) {
            int u = tn + 8 * uu;
            float2 if0 = u2f(acc[2 * uu]);        // m0: (z_i, z_f)
            float2 co0 = u2f(acc[2 * uu + 1]);    // m0: (z_c, z_o)
            float2 if1 = u2f(acc[10 + 2 * uu]);   // m1
            float2 co1 = u2f(acc[10 + 2 * uu + 1]);
            float2 cp = cpre[uu];
            float cn0 = fmaf(hsig(if0.y), cp.x, hsig(if0.x) * tanh_mufu(co0.x));
            float cn1 = fmaf(hsig(if1.y), cp.y, hsig(if1.x) * tanh_mufu(co1.x));
            float hn0 = hsig(co0.y) * tanh_mufu(cn0);
            float hn1 = hsig(co1.y) * tanh_mufu(cn1);
            if (!last)
                g_hc[(size_t)u * (P / 2) + pbase + tm] =
                    make_float4(cn0, cn1, hn0, hn1);
            unsigned long long hn2 = pack2(hn0, hn1);
            FMA2(accF, hn2, Wf2[u]);
            FMA2(accI, hn2, Wi2[u]);
        }
        prF[tn * 32 + tm] = u2f(accF);
        prI[tn * 32 + tm] = u2f(accI);
        __syncthreads();                       // BAR 2: pr ready, xs free

        // ---- epilogue (tid < 64): register operands only ----
        if (tid < 64) {
            int m = tid;
            int coord = base + m;
            int half_ = m & 1, mp = m >> 1;
            float pf = 0.f, pi = 0.f;
#pragma unroll
            for (int w = 0; w < 8; w++) {
                float2 vf = prF[w * 32 + mp];
                float2 vi = prI[w * 32 + mp];
                pf += half_ ? vf.y : vf.x;
                pi += half_ ? vi.y : vi.x;
            }
            float fnew = fmaxf(fmaf(fp_c, Wf_s[40], pf) + bfv, 0.f);
            float inew = fmaxf(fmaf(ip_c, Wi_s[40], pi) + biv, 0.f);
            float pnew = fnew * pold_c - inew * gv_c;
            if (!last) {
                g_fi[coord] = make_float2(fnew, inew);
                g_p[coord] = pnew;
            } else {
                outp[coord] = pnew;
            }
        }
        // next fill overwrites xs only (GEMM done); epilogue threads gate
        // the next BAR 1, so prF/prI stay valid until everyone passes it.
    }
}

// ---------------------------------------------------------------------------
extern "C" void kernel_launch(void* const* d_in, const int* in_sizes, int n_in,
                              void* d_out, int out_size)
{
    const float* feats  = (const float*)d_in[0];
    const float* labels = (const float*)d_in[1];
    const float* params = (const float*)d_in[2];
    const float* kern   = (const float*)d_in[3];
    const float* rkern  = (const float*)d_in[4];
    const float* bias   = (const float*)d_in[5];
    const float* Wf     = (const float*)d_in[6];
    const float* bf     = (const float*)d_in[7];
    const float* Wi     = (const float*)d_in[8];
    const float* bi     = (const float*)d_in[9];
    float* out = (float*)d_out;

    cudaFuncSetAttribute(stepC, cudaFuncAttributeMaxDynamicSharedMemorySize,
                         SMEM_C_BYTES);

    for (int t = 0; t < T; t++) {
        const float* ft = feats  + (size_t)t * B * D;
        const float* lt = labels + (size_t)t * B * C;
        int t0 = (t == 0) ? 1 : 0;
        int last = (t == T - 1) ? 1 : 0;
        stepA<<<256, 256>>>(ft, lt, params, t0);
        stepC<<<NBLK_C, 256, SMEM_C_BYTES>>>(ft, kern, rkern, bias,
                                             Wf, bf, Wi, bi,
                                             params, out, t0, last);
    }
}

// round 16
// speedup vs baseline: 1.0049x; 1.0049x over previous
#include <cuda_runtime.h>
#include <math.h>

// ---------------------------------------------------------------------------
// MetaLearner: coordinate-wise LSTM learned optimizer, 16 sequential steps.
// Consolidated best config (round 14) + unclamped MUFU tanh.
// ---------------------------------------------------------------------------

#define D 512
#define C 256
#define U 40
#define T 16
#define B 64
#define P 131072
#define NZ 160              // 4*U
#define KE 43               // 3 + U   (l0,l1 folded into bias)
#define PREP 10.0f

#define NEGEXPP 4.5399929762484854e-05f   // exp(-10)
#define EXPP    22026.465794806718f       // exp(+10)

#define NBLK_C 444          // 3 blocks per SM

// ---------------- persistent state (no allocations allowed) ----------------
// hc interleaved: per (u, coord-pair) a float4 (c0, c1, h0, h1).
__device__ float4 g_hc[(size_t)U * (P / 2)];
__device__ float g_p[P];
__device__ float2 g_fi[P];               // (f, i)
__device__ __align__(16) float g_e[B * C];
__device__ float g_losspart[256];

// ---------------------------------------------------------------------------
// Unclamped MUFU tanh: ex2.approx(+inf)->inf, rcp.approx(inf)->0 => +1;
// ex2.approx(-inf)->0 => d=1 => -1.  Finite args only (GEMM outputs).
// ---------------------------------------------------------------------------
__device__ __forceinline__ float tanh_mufu(float x)
{
    float y = x * 2.8853900817779268f;            // 2*log2(e)*x
    float ex;
    asm("ex2.approx.f32 %0, %1;" : "=f"(ex) : "f"(y));  // exp(2x)
    float d = ex + 1.0f;
    float r;
    asm("rcp.approx.f32 %0, %1;" : "=f"(r) : "f"(d));
    return fmaf(-2.0f, r, 1.0f);
}

__device__ __forceinline__ float hsig(float x)
{
    return __saturatef(fmaf(0.2f, x, 0.5f));
}

#define FMA2(acc, a, b) \
    asm("fma.rn.f32x2 %0, %1, %2, %0;" : "+l"(acc) : "l"(a), "l"(b))

__device__ __forceinline__ float2 u2f(unsigned long long v)
{
    float2 r;
    asm("mov.b64 {%0, %1}, %2;" : "=f"(r.x), "=f"(r.y) : "l"(v));
    return r;
}
__device__ __forceinline__ unsigned long long pack2(float a, float b)
{
    unsigned long long v;
    asm("mov.b64 %0, {%1, %2};" : "=l"(v) : "f"(a), "f"(b));
    return v;
}

// ---------------------------------------------------------------------------
// Kernel A: preds/e/loss-partials.  grid 256 = b(64) x col-quarter(4).
// ---------------------------------------------------------------------------
__global__ void __launch_bounds__(256) stepA(
    const float* __restrict__ feats_t,
    const float* __restrict__ labels_t,
    const float* __restrict__ params, int t0)
{
    __shared__ float fr[D];
    __shared__ float4 sred[256];
    int tid = threadIdx.x;
    int b = blockIdx.x >> 2;
    int cq = blockIdx.x & 3;

    fr[tid] = feats_t[b * D + tid];
    fr[tid + 256] = feats_t[b * D + tid + 256];
    __syncthreads();

    const float* pm = t0 ? params : g_p;
    const float4* pm4 = (const float4*)pm;
    int cl = tid & 15, ks = tid >> 4;
    int c4 = cq * 16 + cl;
    float4 acc = make_float4(0.f, 0.f, 0.f, 0.f);
    int dbeg = ks * 32;
#pragma unroll 8
    for (int d = dbeg; d < dbeg + 32; d++) {
        float fv = fr[d];
        float4 w = pm4[d * 64 + c4];
        acc.x = fmaf(fv, w.x, acc.x);
        acc.y = fmaf(fv, w.y, acc.y);
        acc.z = fmaf(fv, w.z, acc.z);
        acc.w = fmaf(fv, w.w, acc.w);
    }
    sred[tid] = acc;
    __syncthreads();

    if (tid < 32) {
        float v = 0.f;
        if (tid < 16) {
            float4 s = sred[tid];
#pragma unroll
            for (int k = 1; k < 16; k++) {
                float4 a = sred[k * 16 + tid];
                s.x += a.x; s.y += a.y; s.z += a.z; s.w += a.w;
            }
            int cc = cq * 16 + tid;
            float4 y = ((const float4*)labels_t)[b * 64 + cc];
            float4 df = make_float4(s.x - y.x, s.y - y.y, s.z - y.z, s.w - y.w);
            const float kc = 2.0f / 16384.0f;
            ((float4*)g_e)[b * 64 + cc] =
                make_float4(df.x * kc, df.y * kc, df.z * kc, df.w * kc);
            v = df.x * df.x + df.y * df.y + df.z * df.z + df.w * df.w;
        }
#pragma unroll
        for (int off = 8; off > 0; off >>= 1)
            v += __shfl_xor_sync(0xffffffffu, v, off);
        if (tid == 0) g_losspart[blockIdx.x] = v;
    }
}

// ---------------------------------------------------------------------------
// Kernel C: grads + LSTM + param update. grid = 444 blocks (3/SM) x 256 thr.
// group tiles {256,512,768,512} -> blocks {56,111,166,111}; 4-5 tiles/block.
// Thread (tn,tm): u-set {tn+8j}, coord pair (2tm,2tm+1). 2 barriers/tile.
// ---------------------------------------------------------------------------
#define WP_ULL    (KE * 8 * 10)              // 3440 ull weight pairs
#define ULL_TOT   (WP_ULL + 80)              // + bias pairs = 3520 ull
#define F_WF      0
#define F_WI      41
#define F_SCAL    82
#define F_FCOL    88                          // [3][64] = 192
#define F_GBUF    (F_FCOL + 192)              // 320 floats (nc<=320)
#define F_XS      (F_GBUF + 320)              // 600 (even -> 8B aligned)
#define XS_STR    66
#define F_PR      (F_XS + KE * XS_STR)        // 600+2838=3438 (even)
#define F_TOT     (F_PR + 1024)
#define SMEM_C_BYTES (ULL_TOT * 8 + F_TOT * 4)   // 28160+17848=46008

__global__ void __launch_bounds__(256, 3) stepC(
    const float* __restrict__ feats_t, // [64,512]
    const float* __restrict__ kern,    // [4,5,160]
    const float* __restrict__ rkern,   // [4,40,160]
    const float* __restrict__ bias,    // [4,160]
    const float* __restrict__ Wf,      // [4,41]
    const float* __restrict__ bf,      // [4]
    const float* __restrict__ Wi,      // [4,41]
    const float* __restrict__ bi,      // [4]
    const float* __restrict__ params,  // [P]
    float* __restrict__ outp,
    int t0, int last)
{
    extern __shared__ __align__(16) unsigned long long smU[];
    unsigned long long* Wp  = smU;            // [43][8][10]
    unsigned long long* bp  = smU + WP_ULL;   // [8][10]
    float* smF  = (float*)(smU + ULL_TOT);
    float* Wf_s = smF + F_WF;
    float* Wi_s = smF + F_WI;
    float* scal = smF + F_SCAL;
    float* fcol = smF + F_FCOL;
    float* gbuf = smF + F_GBUF;
    float* xs   = smF + F_XS;
    float2* prF = (float2*)(smF + F_PR);          // [8][32]
    float2* prI = (float2*)(smF + F_PR + 512);    // [8][32]

    int tid = threadIdx.x;
    int blk = blockIdx.x;

    // ---- block -> (group, tile range) ----
    int grp, bi_, nb, nt, t0g;
    if (blk < 56)       { grp = 0; bi_ = blk;       nb = 56;  nt = 256; t0g = 0;    }
    else if (blk < 167) { grp = 1; bi_ = blk - 56;  nb = 111; nt = 512; t0g = 256;  }
    else if (blk < 333) { grp = 2; bi_ = blk - 167; nb = 166; nt = 768; t0g = 768;  }
    else                { grp = 3; bi_ = blk - 333; nb = 111; nt = 512; t0g = 1536; }
    int q = nt / nb, r = nt % nb;
    int tile_start = t0g + bi_ * q + min(bi_, r);
    int ntiles = q + (bi_ < r ? 1 : 0);          // 4 or 5
    int start64 = tile_start * 64;
    int nc = ntiles * 64;                        // <= 320

    // ---- phase 0a: weights (gate-paired, strided u), Wf/Wi, fcol ----
    if (tid < 41) { Wf_s[tid] = Wf[grp * 41 + tid]; Wi_s[tid] = Wi[grp * 41 + tid]; }
    if (tid == 0) { scal[2] = bf[grp]; scal[3] = bi[grp]; }
    int d_lo = start64 >> 8;
    int d_hi = (start64 + nc - 1) >> 8;
    int nd = d_hi - d_lo + 1;                     // <= 3
    for (int idx = tid; idx < nd * 64; idx += 256) {
        int bb = idx & 63, k = idx >> 6;
        fcol[k * 64 + bb] = feats_t[bb * D + d_lo + k];
    }
    // Wp[k][tn][j]: j=2*uu+p; u = tn + 8*uu; p=0 -> (w_i,w_f); p=1 -> (w_c,w_o)
    for (int idx = tid; idx < KE * 80; idx += 256) {
        int k = idx / 80, j8 = idx - k * 80;
        int tn_ = j8 / 10, j = j8 - tn_ * 10;
        int uu = j >> 1, p = j & 1;
        int u = tn_ + 8 * uu;
        int n0 = (p ? 2 : 0) * 40 + u;
        int n1 = (p ? 3 : 1) * 40 + u;
        const float* src = (k < 3) ? (kern + grp * 800 + k * NZ)
                                   : (rkern + grp * 6400 + (k - 3) * NZ);
        Wp[idx] = pack2(src[n0], src[n1]);
    }
    __syncthreads();

    // ---- phase 0b: loss reduce (warp 0) + grads into gbuf (paired) ----
    if (tid < 32) {
        float v = 0.f;
#pragma unroll
        for (int k = 0; k < 8; k++) v += g_losspart[k * 32 + tid];
#pragma unroll
        for (int off = 16; off > 0; off >>= 1)
            v += __shfl_xor_sync(0xffffffffu, v, off);
        if (tid == 0) {
            float L = v * (1.0f / 16384.0f);
            float a = fabsf(L);
            if (a > NEGEXPP) {
                scal[0] = __logf(a) * (1.0f / PREP);
                scal[1] = (L > 0.f) ? 1.f : ((L < 0.f) ? -1.f : 0.f);
            } else {
                scal[0] = -1.f;
                scal[1] = EXPP * L;
            }
        }
    }
    // one thread per coord PAIR: coords 2*tid, 2*tid+1 (same d always:
    // odd index can't cross a 256 boundary). float2 e loads, shared fcol.
    if (tid < nc / 2) {
        int coord0 = start64 + 2 * tid;
        int cc = coord0 & 255;                   // even
        int dk = (coord0 >> 8) - d_lo;
        const float* frow = fcol + dk * 64;
        float acc0 = 0.f, acc1 = 0.f;
#pragma unroll 8
        for (int bb = 0; bb < B; bb++) {
            float2 ev = *(const float2*)(g_e + bb * C + cc);
            float fv = frow[bb];
            acc0 = fmaf(fv, ev.x, acc0);
            acc1 = fmaf(fv, ev.y, acc1);
        }
        gbuf[2 * tid] = acc0;
        gbuf[2 * tid + 1] = acc1;
    }
    __syncthreads();

    // ---- phase 0c: effective bias (l0,l1 folded), gate-paired, strided u ----
    float l0 = scal[0], l1 = scal[1], bfv = scal[2], biv = scal[3];
    if (tid < 80) {
        int tn_ = tid / 10, j = tid - tn_ * 10;
        int uu = j >> 1, p = j & 1;
        int u = tn_ + 8 * uu;
        int n0 = (p ? 2 : 0) * 40 + u;
        int n1 = (p ? 3 : 1) * 40 + u;
        const float* kb = kern + grp * 800;
        float b0 = bias[grp * NZ + n0] + l0 * kb[3 * NZ + n0] + l1 * kb[4 * NZ + n0];
        float b1 = bias[grp * NZ + n1] + l0 * kb[3 * NZ + n1] + l1 * kb[4 * NZ + n1];
        bp[tid] = pack2(b0, b1);
    }

    int tm = tid & 31;            // coord pair (2tm, 2tm+1)
    int tn = tid >> 5;            // u-set {tn + 8j}
    const unsigned long long* wthr = Wp + tn * 10;
    const unsigned long long* bthr = bp + tn * 10;

    for (int it = 0; it < ntiles; it++) {
        int base = start64 + it * 64;
        int rel = it * 64;
        int pbase = base >> 1;                 // hc pair base

        // ---- fill xs + c->regs + epilogue regs (overlaps prev epilogue) ----
        float pold_c = 0.f, gv_c = 0.f, fp_c = 0.f, ip_c = 0.f;
        if (tid < 64) {
            int coord = base + tid;
            pold_c = t0 ? params[coord] : g_p[coord];
            gv_c = gbuf[rel + tid];
            if (!t0) {
                float2 fi = g_fi[coord];
                fp_c = fi.x; ip_c = fi.y;
            }
            float a = fabsf(gv_c);
            float g0, g1;
            if (a > NEGEXPP) {
                g0 = __logf(a) * (1.0f / PREP);
                g1 = (gv_c > 0.f) ? 1.f : ((gv_c < 0.f) ? -1.f : 0.f);
            } else {
                g0 = -1.f;
                g1 = EXPP * gv_c;
            }
            xs[0 * XS_STR + tid] = pold_c;
            xs[1 * XS_STR + tid] = g0;
            xs[2 * XS_STR + tid] = g1;
        }
        float2 cpre[5];
#pragma unroll
        for (int j = 0; j < 5; j++) {
            int u = tn + 8 * j;
            float4 v = t0 ? make_float4(0.f, 0.f, 0.f, 0.f)
                          : g_hc[(size_t)u * (P / 2) + pbase + tm];
            *(float2*)(xs + (3 + u) * XS_STR + 2 * tm) = make_float2(v.z, v.w);
            cpre[j] = make_float2(v.x, v.y);
        }
        __syncthreads();                       // BAR 1: xs ready

        // ---- GEMM: gate-paired FFMA2.  acc[m*10+2uu+p] ----
        unsigned long long acc[20];
#pragma unroll
        for (int j = 0; j < 10; j++) {
            unsigned long long bv = bthr[j];
            acc[j] = bv; acc[10 + j] = bv;
        }
#pragma unroll 2
        for (int k = 0; k < KE; k++) {
            float2 xv = *(const float2*)(xs + k * XS_STR + 2 * tm);
            unsigned long long s0 = pack2(xv.x, xv.x);
            unsigned long long s1 = pack2(xv.y, xv.y);
            const unsigned long long* wp = wthr + k * 80;
            ulonglong2 w01 = *(const ulonglong2*)(wp);
            ulonglong2 w23 = *(const ulonglong2*)(wp + 2);
            ulonglong2 w45 = *(const ulonglong2*)(wp + 4);
            ulonglong2 w67 = *(const ulonglong2*)(wp + 6);
            ulonglong2 w89 = *(const ulonglong2*)(wp + 8);
            FMA2(acc[0], s0, w01.x);  FMA2(acc[10], s1, w01.x);
            FMA2(acc[1], s0, w01.y);  FMA2(acc[11], s1, w01.y);
            FMA2(acc[2], s0, w23.x);  FMA2(acc[12], s1, w23.x);
            FMA2(acc[3], s0, w23.y);  FMA2(acc[13], s1, w23.y);
            FMA2(acc[4], s0, w45.x);  FMA2(acc[14], s1, w45.x);
            FMA2(acc[5], s0, w45.y);  FMA2(acc[15], s1, w45.y);
            FMA2(acc[6], s0, w67.x);  FMA2(acc[16], s1, w67.x);
            FMA2(acc[7], s0, w67.y);  FMA2(acc[17], s1, w67.y);
            FMA2(acc[8], s0, w89.x);  FMA2(acc[18], s1, w89.x);
            FMA2(acc[9], s0, w89.y);  FMA2(acc[19], s1, w89.y);
        }

        // ---- gates + cell update (c from regs) + f/i partials ----
        float pf0 = 0.f, pf1 = 0.f, pi0 = 0.f, pi1 = 0.f;
#pragma unroll
        for (int uu = 0; uu < 5; uu++) {
            int u = tn + 8 * uu;
            float2 if0 = u2f(acc[2 * uu]);        // m0: (z_i, z_f)
            float2 co0 = u2f(acc[2 * uu + 1]);    // m0: (z_c, z_o)
            float2 if1 = u2f(acc[10 + 2 * uu]);   // m1
            float2 co1 = u2f(acc[10 + 2 * uu + 1]);
            float2 cp = cpre[uu];
            float cn0 = fmaf(hsig(if0.y), cp.x, hsig(if0.x) * tanh_mufu(co0.x));
            float cn1 = fmaf(hsig(if1.y), cp.y, hsig(if1.x) * tanh_mufu(co1.x));
            float hn0 = hsig(co0.y) * tanh_mufu(cn0);
            float hn1 = hsig(co1.y) * tanh_mufu(cn1);
            if (!last)
                g_hc[(size_t)u * (P / 2) + pbase + tm] =
                    make_float4(cn0, cn1, hn0, hn1);
            float wf = Wf_s[u], wi = Wi_s[u];
            pf0 = fmaf(hn0, wf, pf0);
            pf1 = fmaf(hn1, wf, pf1);
            pi0 = fmaf(hn0, wi, pi0);
            pi1 = fmaf(hn1, wi, pi1);
        }
        prF[tn * 32 + tm] = make_float2(pf0, pf1);
        prI[tn * 32 + tm] = make_float2(pi0, pi1);
        __syncthreads();                       // BAR 2: pr ready, xs free

        // ---- epilogue (tid < 64): register operands only ----
        if (tid < 64) {
            int m = tid;
            int coord = base + m;
            int half_ = m & 1, mp = m >> 1;
            float pf = 0.f, pi = 0.f;
#pragma unroll
            for (int w = 0; w < 8; w++) {
                float2 vf = prF[w * 32 + mp];
                float2 vi = prI[w * 32 + mp];
                pf += half_ ? vf.y : vf.x;
                pi += half_ ? vi.y : vi.x;
            }
            float fnew = fmaxf(fmaf(fp_c, Wf_s[40], pf) + bfv, 0.f);
            float inew = fmaxf(fmaf(ip_c, Wi_s[40], pi) + biv, 0.f);
            float pnew = fnew * pold_c - inew * gv_c;
            if (!last) {
                g_fi[coord] = make_float2(fnew, inew);
                g_p[coord] = pnew;
            } else {
                outp[coord] = pnew;
            }
        }
        // next fill overwrites xs only (GEMM done); epilogue threads gate
        // the next BAR 1, so prF/prI stay valid until everyone passes it.
    }
}

// ---------------------------------------------------------------------------
extern "C" void kernel_launch(void* const* d_in, const int* in_sizes, int n_in,
                              void* d_out, int out_size)
{
    const float* feats  = (const float*)d_in[0];
    const float* labels = (const float*)d_in[1];
    const float* params = (const float*)d_in[2];
    const float* kern   = (const float*)d_in[3];
    const float* rkern  = (const float*)d_in[4];
    const float* bias   = (const float*)d_in[5];
    const float* Wf     = (const float*)d_in[6];
    const float* bf     = (const float*)d_in[7];
    const float* Wi     = (const float*)d_in[8];
    const float* bi     = (const float*)d_in[9];
    float* out = (float*)d_out;

    cudaFuncSetAttribute(stepC, cudaFuncAttributeMaxDynamicSharedMemorySize,
                         SMEM_C_BYTES);

    for (int t = 0; t < T; t++) {
        const float* ft = feats  + (size_t)t * B * D;
        const float* lt = labels + (size_t)t * B * C;
        int t0 = (t == 0) ? 1 : 0;
        int last = (t == T - 1) ? 1 : 0;
        stepA<<<256, 256>>>(ft, lt, params, t0);
        stepC<<<NBLK_C, 256, SMEM_C_BYTES>>>(ft, kern, rkern, bias,
                                             Wf, bf, Wi, bi,
                                             params, out, t0, last);
    }
}

// round 17
// speedup vs baseline: 1.0286x; 1.0235x over previous
#include <cuda_runtime.h>
#include <math.h>

// ---------------------------------------------------------------------------
// MetaLearner: coordinate-wise LSTM learned optimizer, 16 sequential steps.
// Round-16 base + one-shot packed-weight precompute (prepW) so stepC's
// phase 0a is a coalesced copy instead of a scattered gather+pack.
// ---------------------------------------------------------------------------

#define D 512
#define C 256
#define U 40
#define T 16
#define B 64
#define P 131072
#define NZ 160              // 4*U
#define KE 43               // 3 + U   (l0,l1 folded into bias)
#define PREP 10.0f

#define NEGEXPP 4.5399929762484854e-05f   // exp(-10)
#define EXPP    22026.465794806718f       // exp(+10)

#define NBLK_C 444          // 3 blocks per SM

// ---------------- persistent state (no allocations allowed) ----------------
// hc interleaved: per (u, coord-pair) a float4 (c0, c1, h0, h1).
__device__ float4 g_hc[(size_t)U * (P / 2)];
__device__ float g_p[P];
__device__ float2 g_fi[P];               // (f, i)
__device__ __align__(16) float g_e[B * C];
__device__ float g_losspart[256];
// packed gate-paired weights per group: [4][KE*80] ull
__device__ __align__(16) unsigned long long g_Wpk[4 * KE * 80];

// ---------------------------------------------------------------------------
// Unclamped MUFU tanh: ex2.approx(+inf)->inf, rcp.approx(inf)->0 => +1;
// ex2.approx(-inf)->0 => d=1 => -1.  Finite args only (GEMM outputs).
// ---------------------------------------------------------------------------
__device__ __forceinline__ float tanh_mufu(float x)
{
    float y = x * 2.8853900817779268f;            // 2*log2(e)*x
    float ex;
    asm("ex2.approx.f32 %0, %1;" : "=f"(ex) : "f"(y));  // exp(2x)
    float d = ex + 1.0f;
    float r;
    asm("rcp.approx.f32 %0, %1;" : "=f"(r) : "f"(d));
    return fmaf(-2.0f, r, 1.0f);
}

__device__ __forceinline__ float hsig(float x)
{
    return __saturatef(fmaf(0.2f, x, 0.5f));
}

#define FMA2(acc, a, b) \
    asm("fma.rn.f32x2 %0, %1, %2, %0;" : "+l"(acc) : "l"(a), "l"(b))

__device__ __forceinline__ float2 u2f(unsigned long long v)
{
    float2 r;
    asm("mov.b64 {%0, %1}, %2;" : "=f"(r.x), "=f"(r.y) : "l"(v));
    return r;
}
__device__ __forceinline__ unsigned long long pack2(float a, float b)
{
    unsigned long long v;
    asm("mov.b64 %0, {%1, %2};" : "=l"(v) : "f"(a), "f"(b));
    return v;
}

// ---------------------------------------------------------------------------
// prepW: one-shot packed-weight table build.  grid 16 x 256.
// Layout identical to stepC's Wp: [k][tn][j], j=2*uu+p, u=tn+8*uu,
// p=0 -> (w_i, w_f), p=1 -> (w_c, w_o).
// ---------------------------------------------------------------------------
__global__ void __launch_bounds__(256) prepW(
    const float* __restrict__ kern,    // [4,5,160]
    const float* __restrict__ rkern)   // [4,40,160]
{
    int gid = blockIdx.x * 256 + threadIdx.x;
    int total = 4 * KE * 80;
    for (int idx = gid; idx < total; idx += 16 * 256) {
        int grp = idx / (KE * 80);
        int rem = idx - grp * (KE * 80);
        int k = rem / 80, j8 = rem - k * 80;
        int tn_ = j8 / 10, j = j8 - tn_ * 10;
        int uu = j >> 1, p = j & 1;
        int u = tn_ + 8 * uu;
        int n0 = (p ? 2 : 0) * 40 + u;
        int n1 = (p ? 3 : 1) * 40 + u;
        const float* src = (k < 3) ? (kern + grp * 800 + k * NZ)
                                   : (rkern + grp * 6400 + (k - 3) * NZ);
        g_Wpk[idx] = pack2(src[n0], src[n1]);
    }
}

// ---------------------------------------------------------------------------
// Kernel A: preds/e/loss-partials.  grid 256 = b(64) x col-quarter(4).
// ---------------------------------------------------------------------------
__global__ void __launch_bounds__(256) stepA(
    const float* __restrict__ feats_t,
    const float* __restrict__ labels_t,
    const float* __restrict__ params, int t0)
{
    __shared__ float fr[D];
    __shared__ float4 sred[256];
    int tid = threadIdx.x;
    int b = blockIdx.x >> 2;
    int cq = blockIdx.x & 3;

    fr[tid] = feats_t[b * D + tid];
    fr[tid + 256] = feats_t[b * D + tid + 256];
    __syncthreads();

    const float* pm = t0 ? params : g_p;
    const float4* pm4 = (const float4*)pm;
    int cl = tid & 15, ks = tid >> 4;
    int c4 = cq * 16 + cl;
    float4 acc = make_float4(0.f, 0.f, 0.f, 0.f);
    int dbeg = ks * 32;
#pragma unroll 8
    for (int d = dbeg; d < dbeg + 32; d++) {
        float fv = fr[d];
        float4 w = pm4[d * 64 + c4];
        acc.x = fmaf(fv, w.x, acc.x);
        acc.y = fmaf(fv, w.y, acc.y);
        acc.z = fmaf(fv, w.z, acc.z);
        acc.w = fmaf(fv, w.w, acc.w);
    }
    sred[tid] = acc;
    __syncthreads();

    if (tid < 32) {
        float v = 0.f;
        if (tid < 16) {
            float4 s = sred[tid];
#pragma unroll
            for (int k = 1; k < 16; k++) {
                float4 a = sred[k * 16 + tid];
                s.x += a.x; s.y += a.y; s.z += a.z; s.w += a.w;
            }
            int cc = cq * 16 + tid;
            float4 y = ((const float4*)labels_t)[b * 64 + cc];
            float4 df = make_float4(s.x - y.x, s.y - y.y, s.z - y.z, s.w - y.w);
            const float kc = 2.0f / 16384.0f;
            ((float4*)g_e)[b * 64 + cc] =
                make_float4(df.x * kc, df.y * kc, df.z * kc, df.w * kc);
            v = df.x * df.x + df.y * df.y + df.z * df.z + df.w * df.w;
        }
#pragma unroll
        for (int off = 8; off > 0; off >>= 1)
            v += __shfl_xor_sync(0xffffffffu, v, off);
        if (tid == 0) g_losspart[blockIdx.x] = v;
    }
}

// ---------------------------------------------------------------------------
// Kernel C: grads + LSTM + param update. grid = 444 blocks (3/SM) x 256 thr.
// group tiles {256,512,768,512} -> blocks {56,111,166,111}; 4-5 tiles/block.
// Thread (tn,tm): u-set {tn+8j}, coord pair (2tm,2tm+1). 2 barriers/tile.
// ---------------------------------------------------------------------------
#define WP_ULL    (KE * 8 * 10)              // 3440 ull weight pairs
#define ULL_TOT   (WP_ULL + 80)              // + bias pairs = 3520 ull
#define F_WF      0
#define F_WI      41
#define F_SCAL    82
#define F_FCOL    88                          // [3][64] = 192
#define F_GBUF    (F_FCOL + 192)              // 320 floats (nc<=320)
#define F_XS      (F_GBUF + 320)              // 600 (even -> 8B aligned)
#define XS_STR    66
#define F_PR      (F_XS + KE * XS_STR)        // 600+2838=3438 (even)
#define F_TOT     (F_PR + 1024)
#define SMEM_C_BYTES (ULL_TOT * 8 + F_TOT * 4)   // 28160+17848=46008

__global__ void __launch_bounds__(256, 3) stepC(
    const float* __restrict__ feats_t, // [64,512]
    const float* __restrict__ kern,    // [4,5,160]
    const float* __restrict__ rkern,   // [4,40,160]
    const float* __restrict__ bias,    // [4,160]
    const float* __restrict__ Wf,      // [4,41]
    const float* __restrict__ bf,      // [4]
    const float* __restrict__ Wi,      // [4,41]
    const float* __restrict__ bi,      // [4]
    const float* __restrict__ params,  // [P]
    float* __restrict__ outp,
    int t0, int last)
{
    extern __shared__ __align__(16) unsigned long long smU[];
    unsigned long long* Wp  = smU;            // [43][8][10]
    unsigned long long* bp  = smU + WP_ULL;   // [8][10]
    float* smF  = (float*)(smU + ULL_TOT);
    float* Wf_s = smF + F_WF;
    float* Wi_s = smF + F_WI;
    float* scal = smF + F_SCAL;
    float* fcol = smF + F_FCOL;
    float* gbuf = smF + F_GBUF;
    float* xs   = smF + F_XS;
    float2* prF = (float2*)(smF + F_PR);          // [8][32]
    float2* prI = (float2*)(smF + F_PR + 512);    // [8][32]

    int tid = threadIdx.x;
    int blk = blockIdx.x;

    // ---- block -> (group, tile range) ----
    int grp, bi_, nb, nt, t0g;
    if (blk < 56)       { grp = 0; bi_ = blk;       nb = 56;  nt = 256; t0g = 0;    }
    else if (blk < 167) { grp = 1; bi_ = blk - 56;  nb = 111; nt = 512; t0g = 256;  }
    else if (blk < 333) { grp = 2; bi_ = blk - 167; nb = 166; nt = 768; t0g = 768;  }
    else                { grp = 3; bi_ = blk - 333; nb = 111; nt = 512; t0g = 1536; }
    int q = nt / nb, r = nt % nb;
    int tile_start = t0g + bi_ * q + min(bi_, r);
    int ntiles = q + (bi_ < r ? 1 : 0);          // 4 or 5
    int start64 = tile_start * 64;
    int nc = ntiles * 64;                        // <= 320

    // ---- phase 0a: weights (coalesced copy of precomputed table) ----
    if (tid < 41) { Wf_s[tid] = Wf[grp * 41 + tid]; Wi_s[tid] = Wi[grp * 41 + tid]; }
    if (tid == 0) { scal[2] = bf[grp]; scal[3] = bi[grp]; }
    int d_lo = start64 >> 8;
    int d_hi = (start64 + nc - 1) >> 8;
    int nd = d_hi - d_lo + 1;                     // <= 3
    for (int idx = tid; idx < nd * 64; idx += 256) {
        int bb = idx & 63, k = idx >> 6;
        fcol[k * 64 + bb] = feats_t[bb * D + d_lo + k];
    }
    {
        const ulonglong2* srcW = (const ulonglong2*)(g_Wpk + grp * (KE * 80));
        ulonglong2* dstW = (ulonglong2*)Wp;
#pragma unroll 2
        for (int idx = tid; idx < KE * 40; idx += 256)
            dstW[idx] = srcW[idx];
    }
    __syncthreads();

    // ---- phase 0b: loss reduce (warp 0) + grads into gbuf (paired) ----
    if (tid < 32) {
        float v = 0.f;
#pragma unroll
        for (int k = 0; k < 8; k++) v += g_losspart[k * 32 + tid];
#pragma unroll
        for (int off = 16; off > 0; off >>= 1)
            v += __shfl_xor_sync(0xffffffffu, v, off);
        if (tid == 0) {
            float L = v * (1.0f / 16384.0f);
            float a = fabsf(L);
            if (a > NEGEXPP) {
                scal[0] = __logf(a) * (1.0f / PREP);
                scal[1] = (L > 0.f) ? 1.f : ((L < 0.f) ? -1.f : 0.f);
            } else {
                scal[0] = -1.f;
                scal[1] = EXPP * L;
            }
        }
    }
    // one thread per coord PAIR: coords 2*tid, 2*tid+1 (same d always:
    // odd index can't cross a 256 boundary). float2 e loads, shared fcol.
    if (tid < nc / 2) {
        int coord0 = start64 + 2 * tid;
        int cc = coord0 & 255;                   // even
        int dk = (coord0 >> 8) - d_lo;
        const float* frow = fcol + dk * 64;
        float acc0 = 0.f, acc1 = 0.f;
#pragma unroll 8
        for (int bb = 0; bb < B; bb++) {
            float2 ev = *(const float2*)(g_e + bb * C + cc);
            float fv = frow[bb];
            acc0 = fmaf(fv, ev.x, acc0);
            acc1 = fmaf(fv, ev.y, acc1);
        }
        gbuf[2 * tid] = acc0;
        gbuf[2 * tid + 1] = acc1;
    }
    __syncthreads();

    // ---- phase 0c: effective bias (l0,l1 folded), gate-paired, strided u ----
    float l0 = scal[0], l1 = scal[1], bfv = scal[2], biv = scal[3];
    if (tid < 80) {
        int tn_ = tid / 10, j = tid - tn_ * 10;
        int uu = j >> 1, p = j & 1;
        int u = tn_ + 8 * uu;
        int n0 = (p ? 2 : 0) * 40 + u;
        int n1 = (p ? 3 : 1) * 40 + u;
        const float* kb = kern + grp * 800;
        float b0 = bias[grp * NZ + n0] + l0 * kb[3 * NZ + n0] + l1 * kb[4 * NZ + n0];
        float b1 = bias[grp * NZ + n1] + l0 * kb[3 * NZ + n1] + l1 * kb[4 * NZ + n1];
        bp[tid] = pack2(b0, b1);
    }

    int tm = tid & 31;            // coord pair (2tm, 2tm+1)
    int tn = tid >> 5;            // u-set {tn + 8j}
    const unsigned long long* wthr = Wp + tn * 10;
    const unsigned long long* bthr = bp + tn * 10;

    for (int it = 0; it < ntiles; it++) {
        int base = start64 + it * 64;
        int rel = it * 64;
        int pbase = base >> 1;                 // hc pair base

        // ---- fill xs + c->regs + epilogue regs (overlaps prev epilogue) ----
        float pold_c = 0.f, gv_c = 0.f, fp_c = 0.f, ip_c = 0.f;
        if (tid < 64) {
            int coord = base + tid;
            pold_c = t0 ? params[coord] : g_p[coord];
            gv_c = gbuf[rel + tid];
            if (!t0) {
                float2 fi = g_fi[coord];
                fp_c = fi.x; ip_c = fi.y;
            }
            float a = fabsf(gv_c);
            float g0, g1;
            if (a > NEGEXPP) {
                g0 = __logf(a) * (1.0f / PREP);
                g1 = (gv_c > 0.f) ? 1.f : ((gv_c < 0.f) ? -1.f : 0.f);
            } else {
                g0 = -1.f;
                g1 = EXPP * gv_c;
            }
            xs[0 * XS_STR + tid] = pold_c;
            xs[1 * XS_STR + tid] = g0;
            xs[2 * XS_STR + tid] = g1;
        }
        float2 cpre[5];
#pragma unroll
        for (int j = 0; j < 5; j++) {
            int u = tn + 8 * j;
            float4 v = t0 ? make_float4(0.f, 0.f, 0.f, 0.f)
                          : g_hc[(size_t)u * (P / 2) + pbase + tm];
            *(float2*)(xs + (3 + u) * XS_STR + 2 * tm) = make_float2(v.z, v.w);
            cpre[j] = make_float2(v.x, v.y);
        }
        __syncthreads();                       // BAR 1: xs ready

        // ---- GEMM: gate-paired FFMA2.  acc[m*10+2uu+p] ----
        unsigned long long acc[20];
#pragma unroll
        for (int j = 0; j < 10; j++) {
            unsigned long long bv = bthr[j];
            acc[j] = bv; acc[10 + j] = bv;
        }
#pragma unroll 2
        for (int k = 0; k < KE; k++) {
            float2 xv = *(const float2*)(xs + k * XS_STR + 2 * tm);
            unsigned long long s0 = pack2(xv.x, xv.x);
            unsigned long long s1 = pack2(xv.y, xv.y);
            const unsigned long long* wp = wthr + k * 80;
            ulonglong2 w01 = *(const ulonglong2*)(wp);
            ulonglong2 w23 = *(const ulonglong2*)(wp + 2);
            ulonglong2 w45 = *(const ulonglong2*)(wp + 4);
            ulonglong2 w67 = *(const ulonglong2*)(wp + 6);
            ulonglong2 w89 = *(const ulonglong2*)(wp + 8);
            FMA2(acc[0], s0, w01.x);  FMA2(acc[10], s1, w01.x);
            FMA2(acc[1], s0, w01.y);  FMA2(acc[11], s1, w01.y);
            FMA2(acc[2], s0, w23.x);  FMA2(acc[12], s1, w23.x);
            FMA2(acc[3], s0, w23.y);  FMA2(acc[13], s1, w23.y);
            FMA2(acc[4], s0, w45.x);  FMA2(acc[14], s1, w45.x);
            FMA2(acc[5], s0, w45.y);  FMA2(acc[15], s1, w45.y);
            FMA2(acc[6], s0, w67.x);  FMA2(acc[16], s1, w67.x);
            FMA2(acc[7], s0, w67.y);  FMA2(acc[17], s1, w67.y);
            FMA2(acc[8], s0, w89.x);  FMA2(acc[18], s1, w89.x);
            FMA2(acc[9], s0, w89.y);  FMA2(acc[19], s1, w89.y);
        }

        // ---- gates + cell update (c from regs) + f/i partials ----
        float pf0 = 0.f, pf1 = 0.f, pi0 = 0.f, pi1 = 0.f;
#pragma unroll
        for (int uu = 0; uu < 5; uu++) {
            int u = tn + 8 * uu;
            float2 if0 = u2f(acc[2 * uu]);        // m0: (z_i, z_f)
            float2 co0 = u2f(acc[2 * uu + 1]);    // m0: (z_c, z_o)
            float2 if1 = u2f(acc[10 + 2 * uu]);   // m1
            float2 co1 = u2f(acc[10 + 2 * uu + 1]);
            float2 cp = cpre[uu];
            float cn0 = fmaf(hsig(if0.y), cp.x, hsig(if0.x) * tanh_mufu(co0.x));
            float cn1 = fmaf(hsig(if1.y), cp.y, hsig(if1.x) * tanh_mufu(co1.x));
            float hn0 = hsig(co0.y) * tanh_mufu(cn0);
            float hn1 = hsig(co1.y) * tanh_mufu(cn1);
            if (!last)
                g_hc[(size_t)u * (P / 2) + pbase + tm] =
                    make_float4(cn0, cn1, hn0, hn1);
            float wf = Wf_s[u], wi = Wi_s[u];
            pf0 = fmaf(hn0, wf, pf0);
            pf1 = fmaf(hn1, wf, pf1);
            pi0 = fmaf(hn0, wi, pi0);
            pi1 = fmaf(hn1, wi, pi1);
        }
        prF[tn * 32 + tm] = make_float2(pf0, pf1);
        prI[tn * 32 + tm] = make_float2(pi0, pi1);
        __syncthreads();                       // BAR 2: pr ready, xs free

        // ---- epilogue (tid < 64): register operands only ----
        if (tid < 64) {
            int m = tid;
            int coord = base + m;
            int half_ = m & 1, mp = m >> 1;
            float pf = 0.f, pi = 0.f;
#pragma unroll
            for (int w = 0; w < 8; w++) {
                float2 vf = prF[w * 32 + mp];
                float2 vi = prI[w * 32 + mp];
                pf += half_ ? vf.y : vf.x;
                pi += half_ ? vi.y : vi.x;
            }
            float fnew = fmaxf(fmaf(fp_c, Wf_s[40], pf) + bfv, 0.f);
            float inew = fmaxf(fmaf(ip_c, Wi_s[40], pi) + biv, 0.f);
            float pnew = fnew * pold_c - inew * gv_c;
            if (!last) {
                g_fi[coord] = make_float2(fnew, inew);
                g_p[coord] = pnew;
            } else {
                outp[coord] = pnew;
            }
        }
        // next fill overwrites xs only (GEMM done); epilogue threads gate
        // the next BAR 1, so prF/prI stay valid until everyone passes it.
    }
}

// ---------------------------------------------------------------------------
extern "C" void kernel_launch(void* const* d_in, const int* in_sizes, int n_in,
                              void* d_out, int out_size)
{
    const float* feats  = (const float*)d_in[0];
    const float* labels = (const float*)d_in[1];
    const float* params = (const float*)d_in[2];
    const float* kern   = (const float*)d_in[3];
    const float* rkern  = (const float*)d_in[4];
    const float* bias   = (const float*)d_in[5];
    const float* Wf     = (const float*)d_in[6];
    const float* bf     = (const float*)d_in[7];
    const float* Wi     = (const float*)d_in[8];
    const float* bi     = (const float*)d_in[9];
    float* out = (float*)d_out;

    cudaFuncSetAttribute(stepC, cudaFuncAttributeMaxDynamicSharedMemorySize,
                         SMEM_C_BYTES);

    prepW<<<16, 256>>>(kern, rkern);

    for (int t = 0; t < T; t++) {
        const float* ft = feats  + (size_t)t * B * D;
        const float* lt = labels + (size_t)t * B * C;
        int t0 = (t == 0) ? 1 : 0;
        int last = (t == T - 1) ? 1 : 0;
        stepA<<<256, 256>>>(ft, lt, params, t0);
        stepC<<<NBLK_C, 256, SMEM_C_BYTES>>>(ft, kern, rkern, bias,
                                             Wf, bf, Wi, bi,
                                             params, out, t0, last);
    }
}